// round 1
// baseline (speedup 1.0000x reference)
#include <cuda_runtime.h>
#include <cuda_bf16.h>

// Problem constants
#define BB 4
#define TT 2048
#define NE 32
#define NH 8
#define HD 4
#define NB (TT / 4)          // 512 blocks per (b,h)
#define ROWS_PER_CTA 128
#define NCTA ((BB * TT) / ROWS_PER_CTA)   // 64

// Vbar[b][c][o]: mean over j of v[b, 4j+c, o]  (o = h*4+d)
__device__ float g_vbar[BB][4][NE];

__device__ __forceinline__ float clip100(float v) {
    return fminf(fmaxf(v, -100.0f), 100.0f);
}

// -------- Kernel A: Vbar = (mean_j x[b,4j+c,:]) @ Wv^T + bv --------
__global__ __launch_bounds__(128) void vbar_kernel(
    const float* __restrict__ x, const float* __restrict__ Wv,
    const float* __restrict__ bv)
{
    const int b   = blockIdx.x;
    const int tid = threadIdx.x;            // 0..127 -> (c, e)
    const int c   = tid >> 5;
    const int e   = tid & 31;

    const float* xb = x + (size_t)b * TT * NE;
    float s = 0.0f;
    // address = 128*j + tid -> fully coalesced
    #pragma unroll 4
    for (int j = 0; j < NB; ++j) s += xb[j * 128 + tid];

    __shared__ float xbar[4][32];
    xbar[c][e] = s * (1.0f / (float)NB);
    __syncthreads();

    // 128 outputs per b: thread computes Vbar[c][o], o = e
    const int o = e;
    float acc = bv[o];
    #pragma unroll
    for (int k = 0; k < NE; ++k) acc += xbar[c][k] * Wv[o * NE + k];
    g_vbar[b][c][o] = acc;
}

// -------- Kernel B: q, RXTX, softmax, attn@Vbar, Wp projection --------
__global__ __launch_bounds__(128) void rxtx_attn_kernel(
    const float* __restrict__ x,
    const float* __restrict__ Wq, const float* __restrict__ bq,
    const float* __restrict__ Wp, const float* __restrict__ bp,
    float* __restrict__ out)
{
    __shared__ float sWq[NE][NE];
    __shared__ float sWp[NE][NE];
    __shared__ float sbq[NE];
    __shared__ float sbp[NE];
    __shared__ float sVbar[4][NE];
    __shared__ float sQ[ROWS_PER_CTA][33];   // padded: conflict-free

    const int tid = threadIdx.x;             // one thread == one timestep
    const int tg0 = blockIdx.x * ROWS_PER_CTA;  // global row base in [0, B*T)
    const int b   = tg0 / TT;                // 16 CTAs per batch, aligned

    // Stage weights / biases / Vbar
    #pragma unroll
    for (int i = tid; i < NE * NE; i += ROWS_PER_CTA) {
        sWq[i >> 5][i & 31] = Wq[i];
        sWp[i >> 5][i & 31] = Wp[i];
    }
    if (tid < NE) { sbq[tid] = bq[tid]; sbp[tid] = bp[tid]; }
    sVbar[tid >> 5][tid & 31] = g_vbar[b][tid >> 5][tid & 31];

    // Stage x rows coalesced into sQ
    const float* xblk = x + (size_t)tg0 * NE;
    #pragma unroll
    for (int i = 0; i < NE; ++i) {
        int idx = i * ROWS_PER_CTA + tid;
        sQ[idx >> 5][idx & 31] = xblk[idx];
    }
    __syncthreads();

    // q = clip(x @ Wq^T + bq); each thread owns its row (safe in-place)
    float xr[NE];
    #pragma unroll
    for (int e = 0; e < NE; ++e) xr[e] = sQ[tid][e];
    #pragma unroll
    for (int o = 0; o < NE; ++o) {
        float a = sbq[o];
        #pragma unroll
        for (int e = 0; e < NE; ++e) a += xr[e] * sWq[o][e];
        sQ[tid][o] = clip100(a);
    }
    __syncthreads();

    const int blk = tid & ~3;   // first row of this thread's 4x4 block
    const int r   = tid & 3;    // row within block

    float y[NE];                // attention output, layout o = h*4+d

    #pragma unroll
    for (int h = 0; h < NH; ++h) {
        const int hc = h * 4;
        // X (1-based, row-major 4x4) from the shared q block
        const float X1  = sQ[blk + 0][hc + 0], X2  = sQ[blk + 0][hc + 1],
                    X3  = sQ[blk + 0][hc + 2], X4  = sQ[blk + 0][hc + 3];
        const float X5  = sQ[blk + 1][hc + 0], X6  = sQ[blk + 1][hc + 1],
                    X7  = sQ[blk + 1][hc + 2], X8  = sQ[blk + 1][hc + 3];
        const float X9  = sQ[blk + 2][hc + 0], X10 = sQ[blk + 2][hc + 1],
                    X11 = sQ[blk + 2][hc + 2], X12 = sQ[blk + 2][hc + 3];
        const float X13 = sQ[blk + 3][hc + 0], X14 = sQ[blk + 3][hc + 1],
                    X15 = sQ[blk + 3][hc + 2], X16 = sQ[blk + 3][hc + 3];

        const float m1  = (-X2 + X3 - X4 + X8) * (X8 + X11);
        const float m2  = (X1 - X5 - X6 + X7) * (X15 + X5);
        const float m3  = (-X2 + X12) * (-X10 + X16 + X12);
        const float m4  = (X9 - X6) * (X13 + X9 - X14);
        const float m5  = (X2 + X11) * (-X6 + X15 - X7);
        const float m6  = (X6 + X11) * (X6 + X7 - X11);
        const float m7  = X11 * (X6 + X7);
        const float m8  = X2 * (-X14 - X10 + X6 - X15 + X7 + X16 + X12);
        const float m9  = X6 * (X13 + X9 - X14 - X10 + X6 + X7 - X11);
        const float m10 = (X2 - X3 + X7 + X11 + X4 - X8) * X11;
        const float m11 = (X5 + X6 - X7) * X5;
        const float m12 = (X2 - X3 + X4) * X8;
        const float m13 = (-X1 + X5 + X6 + X3 - X7 + X11) * X15;
        const float m14 = (-X1 + X5 + X6) * (X13 + X9 + X15);
        const float m15 = (X2 + X4 - X8) * (X11 + X16 + X12);
        const float m16 = (X1 - X8) * (X9 - X16);
        const float m17 = X12 * (X10 - X12);
        const float m18 = X9 * (X13 - X14);
        const float m19 = (-X2 + X3) * (-X15 + X7 + X8);
        const float m20 = (X5 + X9 - X8) * X9;
        const float m21 = X8 * (X9 - X8 + X12);
        const float m22 = (-X6 + X7) * (X5 + X7 - X11);
        const float m23 = X1 * (X13 - X5 + X16);
        const float m24 = (-X1 + X4 + X12) * X16;
        const float m25 = (X9 + X2 + X10) * X14;
        const float m26 = (X6 + X10 + X12) * X10;

        const float z1 = m7 - m11 - m12;
        const float z2 = m1 + m12 + m21;
        const float z3 = m3 + m17 - m24;
        const float z4 = m2 + m11 + m23;
        const float z5 = m5 + m7 + m8;
        const float z6 = m4 - m18 - m20;
        const float z7 = m6 - m7 - m9;
        const float z8 = m17 + m18;

        const float c01 = m2 - m5 - z1 + m13 + m19;
        const float c02 = z2 + z3 + m15 + m16;
        const float c03 = z4 - z3 - z5 - m13;
        const float c11 = m1 + m6 - z1 + m10 + m22;
        const float c12 = z2 - z6 + z7 + m10;
        const float c13 = z4 + z6 + m14 + m16;
        const float c22 = m4 - z7 - z8 + m26;
        const float c23 = m3 + z5 + z8 + m25;

        // Select this thread's row of C (corners are exactly 0)
        float a0, a1, a2, a3;
        if      (r == 0) { a0 = 0.0f; a1 = c01;  a2 = c02;  a3 = c03;  }
        else if (r == 1) { a0 = c01;  a1 = c11;  a2 = c12;  a3 = c13;  }
        else if (r == 2) { a0 = c02;  a1 = c12;  a2 = c22;  a3 = c23;  }
        else             { a0 = c03;  a1 = c13;  a2 = c23;  a3 = 0.0f; }

        // clip (post-C) + clip (scores, idempotent) then / sqrt(hd)=2
        a0 = clip100(a0) * 0.5f;
        a1 = clip100(a1) * 0.5f;
        a2 = clip100(a2) * 0.5f;
        a3 = clip100(a3) * 0.5f;

        // stable 4-way softmax
        const float mx = fmaxf(fmaxf(a0, a1), fmaxf(a2, a3));
        const float e0 = __expf(a0 - mx);
        const float e1 = __expf(a1 - mx);
        const float e2 = __expf(a2 - mx);
        const float e3 = __expf(a3 - mx);
        const float inv = 1.0f / (e0 + e1 + e2 + e3);

        #pragma unroll
        for (int d = 0; d < HD; ++d) {
            y[hc + d] = (e0 * sVbar[0][hc + d] + e1 * sVbar[1][hc + d] +
                         e2 * sVbar[2][hc + d] + e3 * sVbar[3][hc + d]) * inv;
        }
    }

    __syncthreads();   // everyone done reading sQ (q values)

    // Final projection: z = y @ Wp^T + bp, staged into sQ for coalesced store
    #pragma unroll
    for (int o = 0; o < NE; ++o) {
        float a = sbp[o];
        #pragma unroll
        for (int e = 0; e < NE; ++e) a += y[e] * sWp[o][e];
        sQ[tid][o] = a;
    }
    __syncthreads();

    float* ob = out + (size_t)tg0 * NE;
    #pragma unroll
    for (int i = 0; i < NE; ++i) {
        int idx = i * ROWS_PER_CTA + tid;
        ob[idx] = sQ[idx >> 5][idx & 31];
    }
}

extern "C" void kernel_launch(void* const* d_in, const int* in_sizes, int n_in,
                              void* d_out, int out_size)
{
    // metadata order: x, Wq, bq, Wk, bk, Wv, bv, Wp, bp   (Wk/bk are dead code)
    const float* x  = (const float*)d_in[0];
    const float* Wq = (const float*)d_in[1];
    const float* bq = (const float*)d_in[2];
    const float* Wv = (const float*)d_in[5];
    const float* bv = (const float*)d_in[6];
    const float* Wp = (const float*)d_in[7];
    const float* bp = (const float*)d_in[8];
    float* out = (float*)d_out;

    vbar_kernel<<<BB, 128>>>(x, Wv, bv);
    rxtx_attn_kernel<<<NCTA, 128>>>(x, Wq, bq, Wp, bp, out);
}

// round 2
// speedup vs baseline: 2.6444x; 2.6444x over previous
#include <cuda_runtime.h>
#include <cuda_bf16.h>

// Problem constants
#define BB 4
#define TT 2048
#define NE 32
#define NH 8
#define HD 4
#define NB (TT / 4)             // 512 4-row blocks per (b,h)
#define ROWS_PER_CTA 32         // kernel B: 32 rows, 4 threads per row
#define NCTA_B ((BB * TT) / ROWS_PER_CTA)   // 256
#define NSLICE 16               // kernel A: 16 slices per batch (128 rows each)

// Partial sums: g_xpart[b][slice][c*32+e] = sum over slice rows (row%4==c) of x[row][e]
__device__ float g_xpart[BB][NSLICE][128];

__device__ __forceinline__ float clip100(float v) {
    return fminf(fmaxf(v, -100.0f), 100.0f);
}

// -------- Kernel A: partial column sums of x, bucketed by (row % 4) --------
// grid = BB*NSLICE = 64, 128 threads. Each CTA covers 128 consecutive rows.
// Element index j*128+tid -> local row = j*4 + (tid>>5), so c = tid>>5 is
// constant per thread and each thread exactly covers its (c, e) bucket.
__global__ __launch_bounds__(128) void xpart_kernel(const float* __restrict__ x)
{
    const int b   = blockIdx.x >> 4;
    const int s   = blockIdx.x & 15;
    const int tid = threadIdx.x;

    const float* xs0 = x + ((size_t)b * TT + (size_t)s * 128) * NE;
    float acc = 0.0f;
    #pragma unroll
    for (int j = 0; j < 32; ++j) acc += xs0[j * 128 + tid];
    g_xpart[b][s][tid] = acc;
}

// -------- Kernel B: Vbar finish + q, RXTX, softmax, attn@Vbar, Wp --------
// 128 threads = 32 rows x 4 parts. Part p owns heads 2p,2p+1 (q/y/z cols 8p..8p+7).
__global__ __launch_bounds__(128) void rxtx_attn_kernel(
    const float* __restrict__ x,
    const float* __restrict__ Wq, const float* __restrict__ bq,
    const float* __restrict__ Wv, const float* __restrict__ bv,
    const float* __restrict__ Wp, const float* __restrict__ bp,
    float* __restrict__ out)
{
    __shared__ float sWq[NE][NE];
    __shared__ float sWp[NE][NE];
    __shared__ float sbq[NE];
    __shared__ float sbp[NE];
    __shared__ float sXbar[4][NE];
    __shared__ float sVb[4][NE];
    __shared__ float sX[ROWS_PER_CTA][33];
    __shared__ float sQ[ROWS_PER_CTA][33];
    __shared__ float sY[ROWS_PER_CTA][33];

    const int tid = threadIdx.x;
    const int r   = tid & 31;          // row within CTA
    const int p   = tid >> 5;          // part / warp id (0..3)
    const int tg0 = blockIdx.x * ROWS_PER_CTA;
    const int b   = tg0 / TT;

    // ---- stage weights / biases (coalesced; later reads are broadcasts) ----
    #pragma unroll
    for (int i = tid; i < NE * NE; i += 128) {
        sWq[i >> 5][i & 31] = Wq[i];
        sWp[i >> 5][i & 31] = Wp[i];
    }
    if (tid < NE) { sbq[tid] = bq[tid]; sbp[tid] = bp[tid]; }

    // ---- finish Vbar reduction: xbar[c][e] with c=p, e=r ----
    {
        float xs = 0.0f;
        #pragma unroll
        for (int s = 0; s < NSLICE; ++s) xs += g_xpart[b][s][tid];
        sXbar[p][r] = xs * (1.0f / (float)NB);
    }

    // ---- stage this CTA's x rows (coalesced) ----
    const float* xblk = x + (size_t)tg0 * NE;
    #pragma unroll
    for (int i = 0; i < 8; ++i) {
        int idx = i * 128 + tid;
        sX[idx >> 5][idx & 31] = xblk[idx];
    }
    __syncthreads();

    // ---- Vbar[c][o] = bv[o] + xbar[c] . Wv[o,:]  (c=p, o=r) ----
    {
        float acc = bv[r];
        #pragma unroll
        for (int e = 0; e < NE; ++e) acc += sXbar[p][e] * Wv[r * NE + e];
        sVb[p][r] = acc;
    }

    // ---- q: thread computes cols [8p, 8p+8) of its row ----
    float xr[NE];
    #pragma unroll
    for (int e = 0; e < NE; ++e) xr[e] = sX[r][e];
    const int o0 = p * 8;
    #pragma unroll
    for (int i = 0; i < 8; ++i) {
        const int o = o0 + i;
        float a = sbq[o];
        #pragma unroll
        for (int e = 0; e < NE; ++e) a += xr[e] * sWq[o][e];
        sQ[r][o] = clip100(a);
    }
    __syncthreads();

    // ---- RXTX + 4-way softmax + attn@Vbar for heads 2p, 2p+1 ----
    const int blk = r & ~3;
    const int rr  = r & 3;

    #pragma unroll
    for (int hh = 0; hh < 2; ++hh) {
        const int hc = o0 + 4 * hh;   // column base of this head

        const float X1  = sQ[blk + 0][hc + 0], X2  = sQ[blk + 0][hc + 1],
                    X3  = sQ[blk + 0][hc + 2], X4  = sQ[blk + 0][hc + 3];
        const float X5  = sQ[blk + 1][hc + 0], X6  = sQ[blk + 1][hc + 1],
                    X7  = sQ[blk + 1][hc + 2], X8  = sQ[blk + 1][hc + 3];
        const float X9  = sQ[blk + 2][hc + 0], X10 = sQ[blk + 2][hc + 1],
                    X11 = sQ[blk + 2][hc + 2], X12 = sQ[blk + 2][hc + 3];
        const float X13 = sQ[blk + 3][hc + 0], X14 = sQ[blk + 3][hc + 1],
                    X15 = sQ[blk + 3][hc + 2], X16 = sQ[blk + 3][hc + 3];

        const float m1  = (-X2 + X3 - X4 + X8) * (X8 + X11);
        const float m2  = (X1 - X5 - X6 + X7) * (X15 + X5);
        const float m3  = (-X2 + X12) * (-X10 + X16 + X12);
        const float m4  = (X9 - X6) * (X13 + X9 - X14);
        const float m5  = (X2 + X11) * (-X6 + X15 - X7);
        const float m6  = (X6 + X11) * (X6 + X7 - X11);
        const float m7  = X11 * (X6 + X7);
        const float m8  = X2 * (-X14 - X10 + X6 - X15 + X7 + X16 + X12);
        const float m9  = X6 * (X13 + X9 - X14 - X10 + X6 + X7 - X11);
        const float m10 = (X2 - X3 + X7 + X11 + X4 - X8) * X11;
        const float m11 = (X5 + X6 - X7) * X5;
        const float m12 = (X2 - X3 + X4) * X8;
        const float m13 = (-X1 + X5 + X6 + X3 - X7 + X11) * X15;
        const float m14 = (-X1 + X5 + X6) * (X13 + X9 + X15);
        const float m15 = (X2 + X4 - X8) * (X11 + X16 + X12);
        const float m16 = (X1 - X8) * (X9 - X16);
        const float m17 = X12 * (X10 - X12);
        const float m18 = X9 * (X13 - X14);
        const float m19 = (-X2 + X3) * (-X15 + X7 + X8);
        const float m20 = (X5 + X9 - X8) * X9;
        const float m21 = X8 * (X9 - X8 + X12);
        const float m22 = (-X6 + X7) * (X5 + X7 - X11);
        const float m23 = X1 * (X13 - X5 + X16);
        const float m24 = (-X1 + X4 + X12) * X16;
        const float m25 = (X9 + X2 + X10) * X14;
        const float m26 = (X6 + X10 + X12) * X10;

        const float z1 = m7 - m11 - m12;
        const float z2 = m1 + m12 + m21;
        const float z3 = m3 + m17 - m24;
        const float z4 = m2 + m11 + m23;
        const float z5 = m5 + m7 + m8;
        const float z6 = m4 - m18 - m20;
        const float z7 = m6 - m7 - m9;
        const float z8 = m17 + m18;

        const float c01 = m2 - m5 - z1 + m13 + m19;
        const float c02 = z2 + z3 + m15 + m16;
        const float c03 = z4 - z3 - z5 - m13;
        const float c11 = m1 + m6 - z1 + m10 + m22;
        const float c12 = z2 - z6 + z7 + m10;
        const float c13 = z4 + z6 + m14 + m16;
        const float c22 = m4 - z7 - z8 + m26;
        const float c23 = m3 + z5 + z8 + m25;

        float a0, a1, a2, a3;
        if      (rr == 0) { a0 = 0.0f; a1 = c01;  a2 = c02;  a3 = c03;  }
        else if (rr == 1) { a0 = c01;  a1 = c11;  a2 = c12;  a3 = c13;  }
        else if (rr == 2) { a0 = c02;  a1 = c12;  a2 = c22;  a3 = c23;  }
        else              { a0 = c03;  a1 = c13;  a2 = c23;  a3 = 0.0f; }

        a0 = clip100(a0) * 0.5f;
        a1 = clip100(a1) * 0.5f;
        a2 = clip100(a2) * 0.5f;
        a3 = clip100(a3) * 0.5f;

        const float mx = fmaxf(fmaxf(a0, a1), fmaxf(a2, a3));
        const float e0 = __expf(a0 - mx);
        const float e1 = __expf(a1 - mx);
        const float e2 = __expf(a2 - mx);
        const float e3 = __expf(a3 - mx);
        const float inv = 1.0f / (e0 + e1 + e2 + e3);

        #pragma unroll
        for (int d = 0; d < HD; ++d) {
            sY[r][hc + d] = (e0 * sVb[0][hc + d] + e1 * sVb[1][hc + d] +
                             e2 * sVb[2][hc + d] + e3 * sVb[3][hc + d]) * inv;
        }
    }
    __syncthreads();

    // ---- projection: z[o] for o in [8p, 8p+8), full y from smem ----
    float yr[NE];
    #pragma unroll
    for (int e = 0; e < NE; ++e) yr[e] = sY[r][e];
    #pragma unroll
    for (int i = 0; i < 8; ++i) {
        const int o = o0 + i;
        float a = sbp[o];
        #pragma unroll
        for (int e = 0; e < NE; ++e) a += yr[e] * sWp[o][e];
        sX[r][o] = a;       // reuse sX as store staging (all reads completed)
    }
    __syncthreads();

    // ---- coalesced store ----
    float* ob = out + (size_t)tg0 * NE;
    #pragma unroll
    for (int i = 0; i < 8; ++i) {
        int idx = i * 128 + tid;
        ob[idx] = sX[idx >> 5][idx & 31];
    }
}

extern "C" void kernel_launch(void* const* d_in, const int* in_sizes, int n_in,
                              void* d_out, int out_size)
{
    // metadata order: x, Wq, bq, Wk, bk, Wv, bv, Wp, bp   (Wk/bk are dead code)
    const float* x  = (const float*)d_in[0];
    const float* Wq = (const float*)d_in[1];
    const float* bq = (const float*)d_in[2];
    const float* Wv = (const float*)d_in[5];
    const float* bv = (const float*)d_in[6];
    const float* Wp = (const float*)d_in[7];
    const float* bp = (const float*)d_in[8];
    float* out = (float*)d_out;

    xpart_kernel<<<BB * NSLICE, 128>>>(x);
    rxtx_attn_kernel<<<NCTA_B, 128>>>(x, Wq, bq, Wv, bv, Wp, bp, out);
}